// round 16
// baseline (speedup 1.0000x reference)
#include <cuda_runtime.h>
#include <cuda_bf16.h>
#include <cstdint>
#include <math.h>

#define DINLINE __device__ __forceinline__

constexpr int B_SAMPLES = 16384;
constexpr int MAP_DIM   = 10000;
constexpr int FEAT      = 128;
constexpr int KC        = 64;                        // K per pipeline chunk
constexpr int NCHUNK    = (MAP_DIM + KC - 1) / KC;   // 157
constexpr int KPAD      = NCHUNK * KC;               // 10048 (zero padded)

constexpr int AP = 72;    // padded A row (bf16 elems): 64 + 8
constexpr int BP = 136;   // padded B row (bf16 elems): 128 + 8

// smem element offsets (bf16 units)
constexpr int AhO = 0;                   // [2][128*AP]
constexpr int AlO = 2 * 128 * AP;        // 18432
constexpr int BhO = 4 * 128 * AP;        // 36864  [2][64*BP]
constexpr int BlO = BhO + 2 * 64 * BP;   // 54272
constexpr int GEMM_SMEM = (4 * 128 * AP + 4 * 64 * BP) * 2;  // 143360 bytes

// MoE smem (floats): xs[128*132] ws[130*128] hs[128*132] w2[1024] b2[8] + lists
constexpr int MOE_SMEM = (128*132 + 130*128 + 128*132 + 1024 + 8) * 4 + (4*128 + 4) * 4;

// ---------------------------------------------------------------------------
// Device scratch (static; no dynamic allocation allowed)
// ---------------------------------------------------------------------------
__device__ __align__(256) __nv_bfloat16 g_Bhi[(size_t)KPAD * FEAT];
__device__ __align__(256) __nv_bfloat16 g_Blo[(size_t)KPAD * FEAT];
__device__ __align__(16)  float         g_xfeat[(size_t)B_SAMPLES * FEAT];

// ---------------------------------------------------------------------------
// PTX helpers (sm_80-baseline instructions only; no tcgen05 — the harness's
// nvcc pipeline targets plain sm_103 PTX, which rejects sm_103a features)
// ---------------------------------------------------------------------------
DINLINE uint32_t smem_u32(const void* p) {
    uint32_t a;
    asm("{ .reg .u64 t; cvta.to.shared.u64 t, %1; cvt.u32.u64 %0, t; }" : "=r"(a) : "l"(p));
    return a;
}
DINLINE void cp_async16(uint32_t s, const void* g) {
    asm volatile("cp.async.ca.shared.global [%0], [%1], 16;" :: "r"(s), "l"(g) : "memory");
}
DINLINE void cp_commit() { asm volatile("cp.async.commit_group;" ::: "memory"); }
DINLINE void cp_wait0()  { asm volatile("cp.async.wait_group 0;" ::: "memory"); }

DINLINE void ldsm4(uint32_t* r, uint32_t addr) {
    asm volatile("ldmatrix.sync.aligned.m8n8.x4.shared.b16 {%0,%1,%2,%3}, [%4];"
                 : "=r"(r[0]), "=r"(r[1]), "=r"(r[2]), "=r"(r[3]) : "r"(addr));
}
DINLINE void ldsm4t(uint32_t* r, uint32_t addr) {
    asm volatile("ldmatrix.sync.aligned.m8n8.x4.trans.shared.b16 {%0,%1,%2,%3}, [%4];"
                 : "=r"(r[0]), "=r"(r[1]), "=r"(r[2]), "=r"(r[3]) : "r"(addr));
}
DINLINE void mma16816(float* d, const uint32_t* a, const uint32_t* b) {
    asm volatile(
        "mma.sync.aligned.m16n8k16.row.col.f32.bf16.bf16.f32 "
        "{%0,%1,%2,%3}, {%4,%5,%6,%7}, {%8,%9}, {%0,%1,%2,%3};"
        : "+f"(d[0]), "+f"(d[1]), "+f"(d[2]), "+f"(d[3])
        : "r"(a[0]), "r"(a[1]), "r"(a[2]), "r"(a[3]), "r"(b[0]), "r"(b[1]));
}
DINLINE uint32_t pack_bf2(float f0, float f1) {
    __nv_bfloat162 t = __floats2bfloat162_rn(f0, f1);
    return *reinterpret_cast<uint32_t*>(&t);
}

// ---------------------------------------------------------------------------
// Kernel 0: split Wf into bf16 hi/lo, row-major [k][n], zero-padded K
// ---------------------------------------------------------------------------
__global__ void prep_kernel(const float* __restrict__ Wf) {
    int c = blockIdx.x;
    int base = c * KC;
    for (int e = threadIdx.x; e < KC * FEAT; e += blockDim.x) {
        int kc = e >> 7;          // 0..63
        int n  = e & 127;         // coalesced across threads
        int k = base + kc;
        float v = (k < MAP_DIM) ? Wf[(size_t)k * FEAT + n] : 0.f;
        __nv_bfloat16 h = __float2bfloat16(v);
        __nv_bfloat16 l = __float2bfloat16(v - __bfloat162float(h));
        size_t o = (size_t)k * FEAT + n;
        g_Bhi[o] = h;
        g_Blo[o] = l;
    }
}

// ---------------------------------------------------------------------------
// Kernel 1: x = leaky(obs @ Wf + bf) via mma.sync bf16, 3-term split
// ---------------------------------------------------------------------------
__global__ __launch_bounds__(256, 1) void gemm_kernel(const float* __restrict__ obs,
                                                      const float* __restrict__ bfv) {
    extern __shared__ __nv_bfloat16 smem[];
    uint32_t sb = smem_u32(smem);

    const int tid  = threadIdx.x;
    const int w    = tid >> 5;
    const int lane = tid & 31;
    const int m0   = blockIdx.x * 128;

    const int wm0 = (w & 3) * 32;       // warp M offset within CTA tile
    const int wn0 = (w >> 2) * 64;      // warp N offset

    // A load mapping: thread -> (row, half of 64-K chunk)
    const int r    = tid >> 1;
    const int half = tid & 1;
    const float* arow = obs + (size_t)(m0 + r) * MAP_DIM;

    float4 aR[8];                        // 32 fp32 staged per chunk

    float acc[2][8][4];
#pragma unroll
    for (int i = 0; i < 2; i++)
#pragma unroll
        for (int j = 0; j < 8; j++)
#pragma unroll
            for (int q = 0; q < 4; q++) acc[i][j][q] = 0.f;

    auto ldgA = [&](int c) {
        int k0 = c * KC + half * 32;
        const float* p = arow + k0;
        if (k0 + 32 <= MAP_DIM) {
#pragma unroll
            for (int j = 0; j < 8; j++) aR[j] = *reinterpret_cast<const float4*>(p + 4 * j);
        } else {
            float t[32];
#pragma unroll
            for (int q = 0; q < 32; q++) t[q] = (k0 + q < MAP_DIM) ? p[q] : 0.f;
#pragma unroll
            for (int j = 0; j < 8; j++) aR[j] = make_float4(t[4*j], t[4*j+1], t[4*j+2], t[4*j+3]);
        }
    };

    auto stsA = [&](int s) {
        __nv_bfloat16* ah = smem + AhO + s * 128 * AP + r * AP + half * 32;
        __nv_bfloat16* al = smem + AlO + s * 128 * AP + r * AP + half * 32;
#pragma unroll
        for (int v = 0; v < 4; v++) {
            float f[8] = { aR[2*v].x, aR[2*v].y, aR[2*v].z, aR[2*v].w,
                           aR[2*v+1].x, aR[2*v+1].y, aR[2*v+1].z, aR[2*v+1].w };
            uint32_t hw[4], lw[4];
#pragma unroll
            for (int p = 0; p < 4; p++) {
                float f0 = f[2*p], f1 = f[2*p+1];
                __nv_bfloat162 hh = __floats2bfloat162_rn(f0, f1);
                hw[p] = *reinterpret_cast<uint32_t*>(&hh);
                lw[p] = pack_bf2(f0 - __low2float(hh), f1 - __high2float(hh));
            }
            reinterpret_cast<uint4*>(ah)[v] = make_uint4(hw[0], hw[1], hw[2], hw[3]);
            reinterpret_cast<uint4*>(al)[v] = make_uint4(lw[0], lw[1], lw[2], lw[3]);
        }
    };

    auto cpB = [&](int c, int s) {
        // chunk c: rows c*64 .. +63, full 128 cols, bf16: 16 x 16B per row
        uint32_t dh = sb + 2u * (BhO + s * 64 * BP);
        uint32_t dl = sb + 2u * (BlO + s * 64 * BP);
        const __nv_bfloat16* gh = g_Bhi + (size_t)c * KC * FEAT;
        const __nv_bfloat16* gl = g_Blo + (size_t)c * KC * FEAT;
#pragma unroll
        for (int i = 0; i < 4; i++) {
            int idx = tid + i * 256;         // 0..1023
            int row = idx >> 4, seg = idx & 15;
            uint32_t so = (uint32_t)(row * BP + seg * 8) * 2u;
            size_t go = (size_t)row * FEAT + seg * 8;
            cp_async16(dh + so, gh + go);
            cp_async16(dl + so, gl + go);
        }
    };

    auto do_mma = [&](int s) {
        uint32_t aAh = sb + 2u * (AhO + s * 128 * AP);
        uint32_t aAl = sb + 2u * (AlO + s * 128 * AP);
        uint32_t aBh = sb + 2u * (BhO + s * 64 * BP);
        uint32_t aBl = sb + 2u * (BlO + s * 64 * BP);
        int lm = lane & 15, lq = lane >> 4;
#pragma unroll
        for (int ks = 0; ks < 4; ks++) {
            uint32_t ah[2][4], al[2][4];
#pragma unroll
            for (int mt = 0; mt < 2; mt++) {
                uint32_t ro = (uint32_t)((wm0 + mt*16 + lm) * AP + ks*16 + lq*8) * 2u;
                ldsm4(ah[mt], aAh + ro);
                ldsm4(al[mt], aAl + ro);
            }
            uint32_t bh[4][4], bl[4][4];
#pragma unroll
            for (int g = 0; g < 4; g++) {
                uint32_t ro = (uint32_t)((ks*16 + lm) * BP + wn0 + g*16 + lq*8) * 2u;
                ldsm4t(bh[g], aBh + ro);
                ldsm4t(bl[g], aBl + ro);
            }
#pragma unroll
            for (int mt = 0; mt < 2; mt++)
#pragma unroll
                for (int g = 0; g < 4; g++) {
                    mma16816(acc[mt][2*g],   ah[mt], &bh[g][0]);
                    mma16816(acc[mt][2*g+1], ah[mt], &bh[g][2]);
                    mma16816(acc[mt][2*g],   ah[mt], &bl[g][0]);
                    mma16816(acc[mt][2*g+1], ah[mt], &bl[g][2]);
                    mma16816(acc[mt][2*g],   al[mt], &bh[g][0]);
                    mma16816(acc[mt][2*g+1], al[mt], &bh[g][2]);
                }
        }
    };

    // ---- prologue: fill stage 0 ----
    ldgA(0);
    cpB(0, 0);
    cp_commit();
    stsA(0);
    cp_wait0();
    __syncthreads();

    // ---- main pipeline (double buffered) ----
    for (int c = 0; c < NCHUNK; c++) {
        int buf = c & 1, nb = buf ^ 1;
        bool more = (c + 1 < NCHUNK);
        if (more) {
            ldgA(c + 1);
            cpB(c + 1, nb);
            cp_commit();
        }
        do_mma(buf);
        __syncthreads();                 // all warps done reading buf
        if (more) {
            stsA(nb);
            cp_wait0();
            __syncthreads();             // nb fully populated for next iter
        }
    }

    // ---- epilogue: bias + leaky, store x to scratch ----
    {
        int rr = lane >> 2, cc = (lane & 3) * 2;
#pragma unroll
        for (int mt = 0; mt < 2; mt++) {
            int mlo = m0 + wm0 + mt * 16 + rr;
#pragma unroll
            for (int ng = 0; ng < 8; ng++) {
                int n = wn0 + ng * 8 + cc;
                float b0 = bfv[n], b1 = bfv[n + 1];
                float v0 = acc[mt][ng][0] + b0; v0 = (v0 >= 0.f) ? v0 : 0.01f * v0;
                float v1 = acc[mt][ng][1] + b1; v1 = (v1 >= 0.f) ? v1 : 0.01f * v1;
                float v2 = acc[mt][ng][2] + b0; v2 = (v2 >= 0.f) ? v2 : 0.01f * v2;
                float v3 = acc[mt][ng][3] + b1; v3 = (v3 >= 0.f) ? v3 : 0.01f * v3;
                *reinterpret_cast<float2*>(&g_xfeat[(size_t)mlo * FEAT + n])       = make_float2(v0, v1);
                *reinterpret_cast<float2*>(&g_xfeat[(size_t)(mlo + 8) * FEAT + n]) = make_float2(v2, v3);
            }
        }
    }
}

// ---------------------------------------------------------------------------
// Kernel 2: routed MoE actor + critic
// ---------------------------------------------------------------------------
__global__ __launch_bounds__(256, 1) void moe_kernel(
    const float* __restrict__ pref,
    const float* __restrict__ Wa1, const float* __restrict__ ba1,
    const float* __restrict__ Wa2, const float* __restrict__ ba2,
    const float* __restrict__ Wc1, const float* __restrict__ bc1,
    const float* __restrict__ Wc2, const float* __restrict__ bc2,
    float* __restrict__ out)
{
    extern __shared__ float sm[];
    float* xs = sm;                       // [128][132]
    float* ws = xs + 128 * 132;           // [130][128]
    float* hs = ws + 130 * 128;           // [128][132]
    float* w2 = hs + 128 * 132;           // [128*8]
    float* b2 = w2 + 1024;                // [8]
    int* lst = reinterpret_cast<int*>(b2 + 8);   // [4][128]
    int* cnt = lst + 512;                 // [4]

    int tid = threadIdx.x;
    int s0 = blockIdx.x * 128;

    if (tid < 4) cnt[tid] = 0;
    {
        int rr = tid >> 1, half = tid & 1;
        const float4* src = reinterpret_cast<const float4*>(
            g_xfeat + (size_t)(s0 + rr) * FEAT + half * 64);
        float* dst = xs + rr * 132 + half * 64;
#pragma unroll
        for (int j = 0; j < 16; j++) reinterpret_cast<float4*>(dst)[j] = src[j];
    }
    __syncthreads();
    if (tid < 128) {
        float p0 = pref[(size_t)(s0 + tid) * 2];
        float p1 = pref[(size_t)(s0 + tid) * 2 + 1];
        xs[tid * 132 + 128] = p0;
        xs[tid * 132 + 129] = p1;
        double th = atan((double)p1 / ((double)p0 + 0.01));
        int idx = (int)floor(th / (3.14159265358979323846 / 8.0));
        idx = idx < 0 ? 0 : (idx > 3 ? 3 : idx);
        int pos = atomicAdd(&cnt[idx], 1);
        lst[idx * 128 + pos] = tid;
    }
    __syncthreads();

    // ---- actor experts (only the routed one per sample) ----
    for (int e = 0; e < 4; e++) {
        int n = cnt[e];
        if (n) {
            const float4* W = reinterpret_cast<const float4*>(Wa1 + (size_t)e * 130 * 128);
            for (int i = tid; i < 130 * 128 / 4; i += 256)
                reinterpret_cast<float4*>(ws)[i] = W[i];
            __syncthreads();
            int nsb = (n + 1) >> 1;
            for (int it = tid; it < nsb * 8; it += 256) {
                int sb = it >> 3, o0 = (it & 7) * 16;
                int r0 = lst[e * 128 + 2 * sb];
                int i1 = (2 * sb + 1 < n) ? (2 * sb + 1) : (n - 1);
                int r1 = lst[e * 128 + i1];
                const float* x0 = xs + r0 * 132;
                const float* x1 = xs + r1 * 132;
                float a0[16], a1[16];
#pragma unroll
                for (int j = 0; j < 16; j++) { a0[j] = 0.f; a1[j] = 0.f; }
                for (int i = 0; i < 130; i++) {
                    float v0 = x0[i], v1 = x1[i];
                    const float* wr = ws + i * 128 + o0;
#pragma unroll
                    for (int j = 0; j < 16; j++) {
                        float w = wr[j];
                        a0[j] += v0 * w;
                        a1[j] += v1 * w;
                    }
                }
#pragma unroll
                for (int j = 0; j < 16; j++) {
                    float bb = ba1[e * 128 + o0 + j];
                    float u0 = a0[j] + bb;
                    hs[r0 * 132 + o0 + j] = (u0 >= 0.f) ? u0 : 0.01f * u0;
                    float u1 = a1[j] + bb;
                    hs[r1 * 132 + o0 + j] = (u1 >= 0.f) ? u1 : 0.01f * u1;
                }
            }
            __syncthreads();
            for (int i = tid; i < 1024; i += 256) w2[i] = Wa2[(size_t)e * 1024 + i];
            if (tid < 8) b2[tid] = ba2[e * 8 + tid];
            __syncthreads();
            for (int it = tid; it < n * 8; it += 256) {
                int si = it >> 3, o = it & 7;
                int rr = lst[e * 128 + si];
                float acc = b2[o];
                const float* h = hs + rr * 132;
                for (int i = 0; i < 128; i++) acc += h[i] * w2[i * 8 + o];
                out[(size_t)(s0 + rr) * 8 + o] = acc;
            }
        }
        __syncthreads();
    }

    // ---- critic ----
    {
        const float4* W = reinterpret_cast<const float4*>(Wc1);
        for (int i = tid; i < 130 * 128 / 4; i += 256)
            reinterpret_cast<float4*>(ws)[i] = W[i];
        __syncthreads();
        for (int it = tid; it < 64 * 8; it += 256) {
            int sb = it >> 3, o0 = (it & 7) * 16;
            int r0 = 2 * sb, r1 = 2 * sb + 1;
            const float* x0 = xs + r0 * 132;
            const float* x1 = xs + r1 * 132;
            float a0[16], a1[16];
#pragma unroll
            for (int j = 0; j < 16; j++) { a0[j] = 0.f; a1[j] = 0.f; }
            for (int i = 0; i < 130; i++) {
                float v0 = x0[i], v1 = x1[i];
                const float* wr = ws + i * 128 + o0;
#pragma unroll
                for (int j = 0; j < 16; j++) {
                    float w = wr[j];
                    a0[j] += v0 * w;
                    a1[j] += v1 * w;
                }
            }
#pragma unroll
            for (int j = 0; j < 16; j++) {
                float bb = bc1[o0 + j];
                float u0 = a0[j] + bb;
                hs[r0 * 132 + o0 + j] = (u0 >= 0.f) ? u0 : 0.01f * u0;
                float u1 = a1[j] + bb;
                hs[r1 * 132 + o0 + j] = (u1 >= 0.f) ? u1 : 0.01f * u1;
            }
        }
        __syncthreads();
        {
            int s = tid >> 1, o = tid & 1;
            float acc = bc2[o];
            const float* h = hs + s * 132;
            for (int i = 0; i < 128; i++) acc += h[i] * Wc2[i * 2 + o];
            out[(size_t)B_SAMPLES * 8 + (size_t)(s0 + s) * 2 + o] = acc;
        }
    }
}

// ---------------------------------------------------------------------------
// Launch
// ---------------------------------------------------------------------------
extern "C" void kernel_launch(void* const* d_in, const int* in_sizes, int n_in,
                              void* d_out, int out_size) {
    const float* obs  = (const float*)d_in[0];
    const float* pref = (const float*)d_in[1];
    const float* Wf   = (const float*)d_in[2];
    const float* bf   = (const float*)d_in[3];
    const float* Wa1  = (const float*)d_in[4];
    const float* ba1  = (const float*)d_in[5];
    const float* Wa2  = (const float*)d_in[6];
    const float* ba2  = (const float*)d_in[7];
    const float* Wc1  = (const float*)d_in[8];
    const float* bc1  = (const float*)d_in[9];
    const float* Wc2  = (const float*)d_in[10];
    const float* bc2  = (const float*)d_in[11];
    float* out = (float*)d_out;

    cudaFuncSetAttribute(gemm_kernel, cudaFuncAttributeMaxDynamicSharedMemorySize, GEMM_SMEM);
    cudaFuncSetAttribute(moe_kernel, cudaFuncAttributeMaxDynamicSharedMemorySize, MOE_SMEM);

    prep_kernel<<<NCHUNK, 256>>>(Wf);
    gemm_kernel<<<B_SAMPLES / 128, 256, GEMM_SMEM>>>(obs, bf);
    moe_kernel<<<B_SAMPLES / 128, 256, MOE_SMEM>>>(pref, Wa1, ba1, Wa2, ba2,
                                                   Wc1, bc1, Wc2, bc2, out);
}

// round 17
// speedup vs baseline: 1.1857x; 1.1857x over previous
#include <cuda_runtime.h>
#include <cuda_fp16.h>
#include <cstdint>
#include <math.h>

#define DINLINE __device__ __forceinline__

constexpr int B_SAMPLES = 16384;
constexpr int MAP_DIM   = 10000;
constexpr int FEAT      = 128;
constexpr int KC        = 64;                        // K per pipeline chunk
constexpr int NCHUNK    = (MAP_DIM + KC - 1) / KC;   // 157
constexpr int KPAD      = NCHUNK * KC;               // 10048 (zero padded)

constexpr int AP = 72;    // padded A row (fp16 elems): 64 + 8
constexpr int BP = 136;   // padded B row (fp16 elems): 128 + 8
constexpr int NSTAGE = 3;

// smem element offsets (fp16 units)
constexpr int AO  = 0;                         // [3][128*AP]  (A hi only)
constexpr int BhO = NSTAGE * 128 * AP;         // [3][64*BP]
constexpr int BlO = BhO + NSTAGE * 64 * BP;    // [3][64*BP]
constexpr int GEMM_SMEM = (NSTAGE * 128 * AP + 2 * NSTAGE * 64 * BP) * 2; // 159744 B

// MoE smem (floats): xs[128*132] ws[130*128] hs[128*132] w2[1024] b2[8] + lists
constexpr int MOE_SMEM = (128*132 + 130*128 + 128*132 + 1024 + 8) * 4 + (4*128 + 4) * 4;

// ---------------------------------------------------------------------------
// Device scratch (static; no dynamic allocation allowed)
// ---------------------------------------------------------------------------
__device__ __align__(256) __half g_Bhi[(size_t)KPAD * FEAT];
__device__ __align__(256) __half g_Blo[(size_t)KPAD * FEAT];
__device__ __align__(16)  float  g_xfeat[(size_t)B_SAMPLES * FEAT];

// ---------------------------------------------------------------------------
// PTX helpers (sm_80-baseline only; harness compiles for plain sm_103 PTX,
// which rejects sm_103a-accelerated features like tcgen05)
// ---------------------------------------------------------------------------
DINLINE uint32_t smem_u32(const void* p) {
    uint32_t a;
    asm("{ .reg .u64 t; cvta.to.shared.u64 t, %1; cvt.u32.u64 %0, t; }" : "=r"(a) : "l"(p));
    return a;
}
DINLINE void cp_async16(uint32_t s, const void* g) {
    asm volatile("cp.async.ca.shared.global [%0], [%1], 16;" :: "r"(s), "l"(g) : "memory");
}
DINLINE void cp_commit() { asm volatile("cp.async.commit_group;" ::: "memory"); }
DINLINE void cp_wait0()  { asm volatile("cp.async.wait_group 0;" ::: "memory"); }
DINLINE void cp_wait1()  { asm volatile("cp.async.wait_group 1;" ::: "memory"); }

DINLINE void ldsm4(uint32_t* r, uint32_t addr) {
    asm volatile("ldmatrix.sync.aligned.m8n8.x4.shared.b16 {%0,%1,%2,%3}, [%4];"
                 : "=r"(r[0]), "=r"(r[1]), "=r"(r[2]), "=r"(r[3]) : "r"(addr));
}
DINLINE void ldsm4t(uint32_t* r, uint32_t addr) {
    asm volatile("ldmatrix.sync.aligned.m8n8.x4.trans.shared.b16 {%0,%1,%2,%3}, [%4];"
                 : "=r"(r[0]), "=r"(r[1]), "=r"(r[2]), "=r"(r[3]) : "r"(addr));
}
DINLINE void mma16816(float* d, const uint32_t* a, const uint32_t* b) {
    asm volatile(
        "mma.sync.aligned.m16n8k16.row.col.f32.f16.f16.f32 "
        "{%0,%1,%2,%3}, {%4,%5,%6,%7}, {%8,%9}, {%0,%1,%2,%3};"
        : "+f"(d[0]), "+f"(d[1]), "+f"(d[2]), "+f"(d[3])
        : "r"(a[0]), "r"(a[1]), "r"(a[2]), "r"(a[3]), "r"(b[0]), "r"(b[1]));
}
DINLINE uint32_t pack_h2(float f0, float f1) {
    __half2 t = __floats2half2_rn(f0, f1);
    return *reinterpret_cast<uint32_t*>(&t);
}

// ---------------------------------------------------------------------------
// Kernel 0: split Wf into fp16 hi/lo, row-major [k][n], zero-padded K
// ---------------------------------------------------------------------------
__global__ void prep_kernel(const float* __restrict__ Wf) {
    int c = blockIdx.x;
    int base = c * KC;
    for (int e = threadIdx.x; e < KC * FEAT; e += blockDim.x) {
        int kc = e >> 7;          // 0..63
        int n  = e & 127;         // coalesced across threads
        int k = base + kc;
        float v = (k < MAP_DIM) ? Wf[(size_t)k * FEAT + n] : 0.f;
        __half h = __float2half_rn(v);
        __half l = __float2half_rn(v - __half2float(h));
        size_t o = (size_t)k * FEAT + n;
        g_Bhi[o] = h;
        g_Blo[o] = l;
    }
}

// ---------------------------------------------------------------------------
// Kernel 1: x = leaky(obs @ Wf + bf) via mma.sync fp16, 2-term B split,
//           3-stage pipeline with one __syncthreads per chunk
// ---------------------------------------------------------------------------
__global__ __launch_bounds__(256, 1) void gemm_kernel(const float* __restrict__ obs,
                                                      const float* __restrict__ bfv) {
    extern __shared__ __half smem[];
    uint32_t sb = smem_u32(smem);

    const int tid  = threadIdx.x;
    const int w    = tid >> 5;
    const int lane = tid & 31;
    const int m0   = blockIdx.x * 128;

    const int wm0 = (w & 3) * 32;       // warp M offset within CTA tile
    const int wn0 = (w >> 2) * 64;      // warp N offset

    // A load mapping: thread -> (row, half of 64-K chunk)
    const int r    = tid >> 1;
    const int half = tid & 1;
    const float* arow = obs + (size_t)(m0 + r) * MAP_DIM;

    float4 aR[8];                        // 32 fp32 staged per chunk

    float acc[2][8][4];
#pragma unroll
    for (int i = 0; i < 2; i++)
#pragma unroll
        for (int j = 0; j < 8; j++)
#pragma unroll
            for (int q = 0; q < 4; q++) acc[i][j][q] = 0.f;

    auto ldgA = [&](int c) {
        int k0 = c * KC + half * 32;
        const float* p = arow + k0;
        if (k0 + 32 <= MAP_DIM) {
#pragma unroll
            for (int j = 0; j < 8; j++) aR[j] = *reinterpret_cast<const float4*>(p + 4 * j);
        } else {
            float t[32];
#pragma unroll
            for (int q = 0; q < 32; q++) t[q] = (k0 + q < MAP_DIM) ? p[q] : 0.f;
#pragma unroll
            for (int j = 0; j < 8; j++) aR[j] = make_float4(t[4*j], t[4*j+1], t[4*j+2], t[4*j+3]);
        }
    };

    auto stsA = [&](int s) {
        __half* ah = smem + AO + s * 128 * AP + r * AP + half * 32;
#pragma unroll
        for (int v = 0; v < 4; v++) {
            uint32_t hw[4];
            hw[0] = pack_h2(aR[2*v].x,   aR[2*v].y);
            hw[1] = pack_h2(aR[2*v].z,   aR[2*v].w);
            hw[2] = pack_h2(aR[2*v+1].x, aR[2*v+1].y);
            hw[3] = pack_h2(aR[2*v+1].z, aR[2*v+1].w);
            reinterpret_cast<uint4*>(ah)[v] = make_uint4(hw[0], hw[1], hw[2], hw[3]);
        }
    };

    auto cpB = [&](int c, int s) {
        uint32_t dh = sb + 2u * (BhO + s * 64 * BP);
        uint32_t dl = sb + 2u * (BlO + s * 64 * BP);
        const __half* gh = g_Bhi + (size_t)c * KC * FEAT;
        const __half* gl = g_Blo + (size_t)c * KC * FEAT;
#pragma unroll
        for (int i = 0; i < 4; i++) {
            int idx = tid + i * 256;         // 0..1023
            int row = idx >> 4, seg = idx & 15;
            uint32_t so = (uint32_t)(row * BP + seg * 8) * 2u;
            size_t go = (size_t)row * FEAT + seg * 8;
            cp_async16(dh + so, gh + go);
            cp_async16(dl + so, gl + go);
        }
    };

    auto do_mma = [&](int s) {
        uint32_t aA  = sb + 2u * (AO  + s * 128 * AP);
        uint32_t aBh = sb + 2u * (BhO + s * 64 * BP);
        uint32_t aBl = sb + 2u * (BlO + s * 64 * BP);
        int lm = lane & 15, lq = lane >> 4;
#pragma unroll
        for (int ks = 0; ks < 4; ks++) {
            uint32_t a[2][4];
#pragma unroll
            for (int mt = 0; mt < 2; mt++) {
                uint32_t ro = (uint32_t)((wm0 + mt*16 + lm) * AP + ks*16 + lq*8) * 2u;
                ldsm4(a[mt], aA + ro);
            }
            uint32_t bh[4][4], bl[4][4];
#pragma unroll
            for (int g = 0; g < 4; g++) {
                uint32_t ro = (uint32_t)((ks*16 + lm) * BP + wn0 + g*16 + lq*8) * 2u;
                ldsm4t(bh[g], aBh + ro);
                ldsm4t(bl[g], aBl + ro);
            }
#pragma unroll
            for (int mt = 0; mt < 2; mt++)
#pragma unroll
                for (int g = 0; g < 4; g++) {
                    mma16816(acc[mt][2*g],   a[mt], &bh[g][0]);
                    mma16816(acc[mt][2*g+1], a[mt], &bh[g][2]);
                    mma16816(acc[mt][2*g],   a[mt], &bl[g][0]);
                    mma16816(acc[mt][2*g+1], a[mt], &bl[g][2]);
                }
        }
    };

    // ---- prologue: fill stages 0 and 1 ----
    ldgA(0); cpB(0, 0); cp_commit(); stsA(0);
    ldgA(1); cpB(1, 1); cp_commit(); stsA(1);
    cp_wait0();
    __syncthreads();

    // ---- main pipeline (3-stage, one sync per chunk) ----
    int stage = 0;
    for (int c = 0; c < NCHUNK; c++) {
        int s = stage;                              // c % 3
        int s2 = (stage + 2 >= NSTAGE) ? stage + 2 - NSTAGE : stage + 2;   // (c+2)%3
        bool more2 = (c + 2 < NCHUNK);
        if (more2) {
            ldgA(c + 2);                            // LDG latency hidden under MMA
            cpB(c + 2, s2);
            cp_commit();
        }
        do_mma(s);
        if (more2) stsA(s2);                        // stage s2 free: MMA(c-1) done + synced
        if (more2) cp_wait1(); else cp_wait0();     // stage (c+1)%3 B complete
        __syncthreads();
        stage = (stage + 1 == NSTAGE) ? 0 : stage + 1;
    }

    // ---- epilogue: bias + leaky, store x to scratch ----
    {
        int rr = lane >> 2, cc = (lane & 3) * 2;
#pragma unroll
        for (int mt = 0; mt < 2; mt++) {
            int mlo = m0 + wm0 + mt * 16 + rr;
#pragma unroll
            for (int ng = 0; ng < 8; ng++) {
                int n = wn0 + ng * 8 + cc;
                float b0 = bfv[n], b1 = bfv[n + 1];
                float v0 = acc[mt][ng][0] + b0; v0 = (v0 >= 0.f) ? v0 : 0.01f * v0;
                float v1 = acc[mt][ng][1] + b1; v1 = (v1 >= 0.f) ? v1 : 0.01f * v1;
                float v2 = acc[mt][ng][2] + b0; v2 = (v2 >= 0.f) ? v2 : 0.01f * v2;
                float v3 = acc[mt][ng][3] + b1; v3 = (v3 >= 0.f) ? v3 : 0.01f * v3;
                *reinterpret_cast<float2*>(&g_xfeat[(size_t)mlo * FEAT + n])       = make_float2(v0, v1);
                *reinterpret_cast<float2*>(&g_xfeat[(size_t)(mlo + 8) * FEAT + n]) = make_float2(v2, v3);
            }
        }
    }
}

// ---------------------------------------------------------------------------
// Kernel 2: routed MoE actor + critic
// ---------------------------------------------------------------------------
__global__ __launch_bounds__(256, 1) void moe_kernel(
    const float* __restrict__ pref,
    const float* __restrict__ Wa1, const float* __restrict__ ba1,
    const float* __restrict__ Wa2, const float* __restrict__ ba2,
    const float* __restrict__ Wc1, const float* __restrict__ bc1,
    const float* __restrict__ Wc2, const float* __restrict__ bc2,
    float* __restrict__ out)
{
    extern __shared__ float sm[];
    float* xs = sm;                       // [128][132]
    float* ws = xs + 128 * 132;           // [130][128]
    float* hs = ws + 130 * 128;           // [128][132]
    float* w2 = hs + 128 * 132;           // [128*8]
    float* b2 = w2 + 1024;                // [8]
    int* lst = reinterpret_cast<int*>(b2 + 8);   // [4][128]
    int* cnt = lst + 512;                 // [4]

    int tid = threadIdx.x;
    int s0 = blockIdx.x * 128;

    if (tid < 4) cnt[tid] = 0;
    {
        int rr = tid >> 1, half = tid & 1;
        const float4* src = reinterpret_cast<const float4*>(
            g_xfeat + (size_t)(s0 + rr) * FEAT + half * 64);
        float* dst = xs + rr * 132 + half * 64;
#pragma unroll
        for (int j = 0; j < 16; j++) reinterpret_cast<float4*>(dst)[j] = src[j];
    }
    __syncthreads();
    if (tid < 128) {
        float p0 = pref[(size_t)(s0 + tid) * 2];
        float p1 = pref[(size_t)(s0 + tid) * 2 + 1];
        xs[tid * 132 + 128] = p0;
        xs[tid * 132 + 129] = p1;
        double th = atan((double)p1 / ((double)p0 + 0.01));
        int idx = (int)floor(th / (3.14159265358979323846 / 8.0));
        idx = idx < 0 ? 0 : (idx > 3 ? 3 : idx);
        int pos = atomicAdd(&cnt[idx], 1);
        lst[idx * 128 + pos] = tid;
    }
    __syncthreads();

    // ---- actor experts (only the routed one per sample) ----
    for (int e = 0; e < 4; e++) {
        int n = cnt[e];
        if (n) {
            const float4* W = reinterpret_cast<const float4*>(Wa1 + (size_t)e * 130 * 128);
            for (int i = tid; i < 130 * 128 / 4; i += 256)
                reinterpret_cast<float4*>(ws)[i] = W[i];
            __syncthreads();
            int nsb = (n + 1) >> 1;
            for (int it = tid; it < nsb * 8; it += 256) {
                int sb = it >> 3, o0 = (it & 7) * 16;
                int r0 = lst[e * 128 + 2 * sb];
                int i1 = (2 * sb + 1 < n) ? (2 * sb + 1) : (n - 1);
                int r1 = lst[e * 128 + i1];
                const float* x0 = xs + r0 * 132;
                const float* x1 = xs + r1 * 132;
                float a0[16], a1[16];
#pragma unroll
                for (int j = 0; j < 16; j++) { a0[j] = 0.f; a1[j] = 0.f; }
                for (int i = 0; i < 130; i++) {
                    float v0 = x0[i], v1 = x1[i];
                    const float* wr = ws + i * 128 + o0;
#pragma unroll
                    for (int j = 0; j < 16; j++) {
                        float w = wr[j];
                        a0[j] += v0 * w;
                        a1[j] += v1 * w;
                    }
                }
#pragma unroll
                for (int j = 0; j < 16; j++) {
                    float bb = ba1[e * 128 + o0 + j];
                    float u0 = a0[j] + bb;
                    hs[r0 * 132 + o0 + j] = (u0 >= 0.f) ? u0 : 0.01f * u0;
                    float u1 = a1[j] + bb;
                    hs[r1 * 132 + o0 + j] = (u1 >= 0.f) ? u1 : 0.01f * u1;
                }
            }
            __syncthreads();
            for (int i = tid; i < 1024; i += 256) w2[i] = Wa2[(size_t)e * 1024 + i];
            if (tid < 8) b2[tid] = ba2[e * 8 + tid];
            __syncthreads();
            for (int it = tid; it < n * 8; it += 256) {
                int si = it >> 3, o = it & 7;
                int rr = lst[e * 128 + si];
                float acc = b2[o];
                const float* h = hs + rr * 132;
                for (int i = 0; i < 128; i++) acc += h[i] * w2[i * 8 + o];
                out[(size_t)(s0 + rr) * 8 + o] = acc;
            }
        }
        __syncthreads();
    }

    // ---- critic ----
    {
        const float4* W = reinterpret_cast<const float4*>(Wc1);
        for (int i = tid; i < 130 * 128 / 4; i += 256)
            reinterpret_cast<float4*>(ws)[i] = W[i];
        __syncthreads();
        for (int it = tid; it < 64 * 8; it += 256) {
            int sb = it >> 3, o0 = (it & 7) * 16;
            int r0 = 2 * sb, r1 = 2 * sb + 1;
            const float* x0 = xs + r0 * 132;
            const float* x1 = xs + r1 * 132;
            float a0[16], a1[16];
#pragma unroll
            for (int j = 0; j < 16; j++) { a0[j] = 0.f; a1[j] = 0.f; }
            for (int i = 0; i < 130; i++) {
                float v0 = x0[i], v1 = x1[i];
                const float* wr = ws + i * 128 + o0;
#pragma unroll
                for (int j = 0; j < 16; j++) {
                    float w = wr[j];
                    a0[j] += v0 * w;
                    a1[j] += v1 * w;
                }
            }
#pragma unroll
            for (int j = 0; j < 16; j++) {
                float bb = bc1[o0 + j];
                float u0 = a0[j] + bb;
                hs[r0 * 132 + o0 + j] = (u0 >= 0.f) ? u0 : 0.01f * u0;
                float u1 = a1[j] + bb;
                hs[r1 * 132 + o0 + j] = (u1 >= 0.f) ? u1 : 0.01f * u1;
            }
        }
        __syncthreads();
        {
            int s = tid >> 1, o = tid & 1;
            float acc = bc2[o];
            const float* h = hs + s * 132;
            for (int i = 0; i < 128; i++) acc += h[i] * Wc2[i * 2 + o];
            out[(size_t)B_SAMPLES * 8 + (size_t)(s0 + s) * 2 + o] = acc;
        }
    }
}

// ---------------------------------------------------------------------------
// Launch
// ---------------------------------------------------------------------------
extern "C" void kernel_launch(void* const* d_in, const int* in_sizes, int n_in,
                              void* d_out, int out_size) {
    const float* obs  = (const float*)d_in[0];
    const float* pref = (const float*)d_in[1];
    const float* Wf   = (const float*)d_in[2];
    const float* bf   = (const float*)d_in[3];
    const float* Wa1  = (const float*)d_in[4];
    const float* ba1  = (const float*)d_in[5];
    const float* Wa2  = (const float*)d_in[6];
    const float* ba2  = (const float*)d_in[7];
    const float* Wc1  = (const float*)d_in[8];
    const float* bc1  = (const float*)d_in[9];
    const float* Wc2  = (const float*)d_in[10];
    const float* bc2  = (const float*)d_in[11];
    float* out = (float*)d_out;

    cudaFuncSetAttribute(gemm_kernel, cudaFuncAttributeMaxDynamicSharedMemorySize, GEMM_SMEM);
    cudaFuncSetAttribute(moe_kernel, cudaFuncAttributeMaxDynamicSharedMemorySize, MOE_SMEM);

    prep_kernel<<<NCHUNK, 256>>>(Wf);
    gemm_kernel<<<B_SAMPLES / 128, 256, GEMM_SMEM>>>(obs, bf);
    moe_kernel<<<B_SAMPLES / 128, 256, MOE_SMEM>>>(pref, Wa1, ba1, Wa2, ba2,
                                                   Wc1, bc1, Wc2, bc2, out);
}